// round 1
// baseline (speedup 1.0000x reference)
#include <cuda_runtime.h>
#include <math.h>

#define B_ 512
#define T_ 256
#define E_ 384
#define H_ 64
#define M_ (B_ * T_)   // 131072

// Scratch for projected q, k, v (33.5 MB each) — static device globals, no runtime alloc.
__device__ float g_q[(size_t)M_ * H_];
__device__ float g_k[(size_t)M_ * H_];
__device__ float g_v[(size_t)M_ * H_];

// ---------------------------------------------------------------------------
// Kernel 1: QKV projection. C[131072 x 64] = X[131072 x 384] * W[384 x 64]
// grid = (M/64, 3); blockIdx.y selects Wq/Wk/Wv.
// 64x64 output tile, K-chunks of 32, 4x4 register micro-tile per thread.
// ---------------------------------------------------------------------------
__global__ __launch_bounds__(256) void qkv_kernel(
    const float* __restrict__ x,
    const float* __restrict__ Wq,
    const float* __restrict__ Wk,
    const float* __restrict__ Wv)
{
    __shared__ float Xs[64][36];   // stride 36: keeps float4 alignment, avoids bank conflicts
    __shared__ float Ws[32][64];

    const int mt = blockIdx.x;
    const float* W;
    float* outp;
    if (blockIdx.y == 0)      { W = Wq; outp = g_q; }
    else if (blockIdx.y == 1) { W = Wk; outp = g_k; }
    else                      { W = Wv; outp = g_v; }

    const int tid = threadIdx.x;
    const int ty = tid >> 4;      // 0..15  (row group)
    const int tx = tid & 15;      // 0..15  (col group)

    float acc[4][4] = {};

    for (int k0 = 0; k0 < E_; k0 += 32) {
        // Load X tile: 64 rows x 32 cols = 512 float4
        #pragma unroll
        for (int f = tid; f < 512; f += 256) {
            int r = f >> 3, c4 = f & 7;
            float4 v = *(const float4*)&x[(size_t)(mt * 64 + r) * E_ + k0 + c4 * 4];
            *(float4*)&Xs[r][c4 * 4] = v;
        }
        // Load W tile: 32 rows x 64 cols = 512 float4
        #pragma unroll
        for (int f = tid; f < 512; f += 256) {
            int r = f >> 4, c4 = f & 15;
            *(float4*)&Ws[r][c4 * 4] = *(const float4*)&W[(size_t)(k0 + r) * H_ + c4 * 4];
        }
        __syncthreads();

        #pragma unroll
        for (int kk = 0; kk < 32; kk++) {
            float a0 = Xs[ty * 4 + 0][kk];
            float a1 = Xs[ty * 4 + 1][kk];
            float a2 = Xs[ty * 4 + 2][kk];
            float a3 = Xs[ty * 4 + 3][kk];
            float4 bv = *(float4*)&Ws[kk][tx * 4];
            acc[0][0] += a0 * bv.x; acc[0][1] += a0 * bv.y; acc[0][2] += a0 * bv.z; acc[0][3] += a0 * bv.w;
            acc[1][0] += a1 * bv.x; acc[1][1] += a1 * bv.y; acc[1][2] += a1 * bv.z; acc[1][3] += a1 * bv.w;
            acc[2][0] += a2 * bv.x; acc[2][1] += a2 * bv.y; acc[2][2] += a2 * bv.z; acc[2][3] += a2 * bv.w;
            acc[3][0] += a3 * bv.x; acc[3][1] += a3 * bv.y; acc[3][2] += a3 * bv.z; acc[3][3] += a3 * bv.w;
        }
        __syncthreads();
    }

    #pragma unroll
    for (int i = 0; i < 4; i++) {
        float4 v = make_float4(acc[i][0], acc[i][1], acc[i][2], acc[i][3]);
        *(float4*)&outp[(size_t)(mt * 64 + ty * 4 + i) * H_ + tx * 4] = v;
    }
}

// ---------------------------------------------------------------------------
// Kernel 2: flash attention with online softmax.
// grid = (T/64, B). One block processes a 64-row q-tile of one batch;
// streams 64-wide K/V tiles kt = 0..qt (causal tile skipping).
// Dynamic smem layout:
//   Qs : 64*64 floats           (q tile, row-major)
//   KP : 64*68 floats           (K transposed [h][c], later overlaid by P [r][c])
//   Vs : 64*64 floats           (V tile, row-major)
// ---------------------------------------------------------------------------
#define KP_STRIDE 68
#define ATTN_SMEM_FLOATS (64 * 64 + 64 * KP_STRIDE + 64 * 64)
#define ATTN_SMEM_BYTES  (ATTN_SMEM_FLOATS * 4)

__global__ __launch_bounds__(256) void attn_kernel(float* __restrict__ out)
{
    extern __shared__ float sm[];
    float* Qs = sm;                       // 4096 floats
    float* KP = sm + 4096;                // 64*68 floats
    float* Vs = sm + 4096 + 64 * KP_STRIDE;

    const int qt = blockIdx.x;
    const int b  = blockIdx.y;
    const int tid = threadIdx.x;
    const int ty = tid >> 4;
    const int tx = tid & 15;

    // Load Q tile
    const float* qp = g_q + ((size_t)b * T_ + qt * 64) * H_;
    #pragma unroll
    for (int f = tid; f < 1024; f += 256) {
        int r = f >> 4, c4 = f & 15;
        *(float4*)&Qs[r * 64 + c4 * 4] = *(const float4*)&qp[r * 64 + c4 * 4];
    }

    float acc[4][4] = {};
    float m_i[4], l_i[4];
    #pragma unroll
    for (int i = 0; i < 4; i++) { m_i[i] = -1e30f; l_i[i] = 0.0f; }

    __syncthreads();

    for (int kt = 0; kt <= qt; kt++) {
        const float* kp = g_k + ((size_t)b * T_ + kt * 64) * H_;
        const float* vp = g_v + ((size_t)b * T_ + kt * 64) * H_;

        // Load K transposed (KP[h][c]) and V row-major
        #pragma unroll
        for (int f = tid; f < 1024; f += 256) {
            int c = f >> 4, h4 = f & 15;
            float4 kv = *(const float4*)&kp[c * 64 + h4 * 4];
            KP[(h4 * 4 + 0) * KP_STRIDE + c] = kv.x;
            KP[(h4 * 4 + 1) * KP_STRIDE + c] = kv.y;
            KP[(h4 * 4 + 2) * KP_STRIDE + c] = kv.z;
            KP[(h4 * 4 + 3) * KP_STRIDE + c] = kv.w;
            *(float4*)&Vs[c * 64 + h4 * 4] = *(const float4*)&vp[c * 64 + h4 * 4];
        }
        __syncthreads();

        // S = Q * K^T for this 64x64 tile (4x4 micro-tile per thread)
        float s[4][4] = {};
        #pragma unroll
        for (int h = 0; h < 64; h++) {
            float a0 = Qs[(ty * 4 + 0) * 64 + h];
            float a1 = Qs[(ty * 4 + 1) * 64 + h];
            float a2 = Qs[(ty * 4 + 2) * 64 + h];
            float a3 = Qs[(ty * 4 + 3) * 64 + h];
            float4 bv = *(float4*)&KP[h * KP_STRIDE + tx * 4];
            s[0][0] += a0 * bv.x; s[0][1] += a0 * bv.y; s[0][2] += a0 * bv.z; s[0][3] += a0 * bv.w;
            s[1][0] += a1 * bv.x; s[1][1] += a1 * bv.y; s[1][2] += a1 * bv.z; s[1][3] += a1 * bv.w;
            s[2][0] += a2 * bv.x; s[2][1] += a2 * bv.y; s[2][2] += a2 * bv.z; s[2][3] += a2 * bv.w;
            s[3][0] += a3 * bv.x; s[3][1] += a3 * bv.y; s[3][2] += a3 * bv.z; s[3][3] += a3 * bv.w;
        }

        const float scale = 0.125f;  // 1/sqrt(64)
        if (kt == qt) {
            #pragma unroll
            for (int i = 0; i < 4; i++)
                #pragma unroll
                for (int j = 0; j < 4; j++)
                    s[i][j] = (tx * 4 + j <= ty * 4 + i) ? s[i][j] * scale : -1e30f;
        } else {
            #pragma unroll
            for (int i = 0; i < 4; i++)
                #pragma unroll
                for (int j = 0; j < 4; j++)
                    s[i][j] *= scale;
        }

        // Online softmax: row max, exp, row sum (16-lane shuffle reductions)
        float p[4][4];
        float corr[4];
        #pragma unroll
        for (int i = 0; i < 4; i++) {
            float mx = fmaxf(fmaxf(s[i][0], s[i][1]), fmaxf(s[i][2], s[i][3]));
            mx = fmaxf(mx, __shfl_xor_sync(0xffffffffu, mx, 8));
            mx = fmaxf(mx, __shfl_xor_sync(0xffffffffu, mx, 4));
            mx = fmaxf(mx, __shfl_xor_sync(0xffffffffu, mx, 2));
            mx = fmaxf(mx, __shfl_xor_sync(0xffffffffu, mx, 1));
            float mnew = fmaxf(m_i[i], mx);
            corr[i] = __expf(m_i[i] - mnew);
            p[i][0] = __expf(s[i][0] - mnew);
            p[i][1] = __expf(s[i][1] - mnew);
            p[i][2] = __expf(s[i][2] - mnew);
            p[i][3] = __expf(s[i][3] - mnew);
            float ts = p[i][0] + p[i][1] + p[i][2] + p[i][3];
            ts += __shfl_xor_sync(0xffffffffu, ts, 8);
            ts += __shfl_xor_sync(0xffffffffu, ts, 4);
            ts += __shfl_xor_sync(0xffffffffu, ts, 2);
            ts += __shfl_xor_sync(0xffffffffu, ts, 1);
            l_i[i] = l_i[i] * corr[i] + ts;
            m_i[i] = mnew;
            acc[i][0] *= corr[i]; acc[i][1] *= corr[i];
            acc[i][2] *= corr[i]; acc[i][3] *= corr[i];
        }

        // All threads done reading KP (S phase) before P overlays it
        __syncthreads();
        #pragma unroll
        for (int i = 0; i < 4; i++)
            *(float4*)&KP[(ty * 4 + i) * KP_STRIDE + tx * 4] =
                make_float4(p[i][0], p[i][1], p[i][2], p[i][3]);
        __syncthreads();

        // O += P * V
        #pragma unroll
        for (int c = 0; c < 64; c++) {
            float a0 = KP[(ty * 4 + 0) * KP_STRIDE + c];
            float a1 = KP[(ty * 4 + 1) * KP_STRIDE + c];
            float a2 = KP[(ty * 4 + 2) * KP_STRIDE + c];
            float a3 = KP[(ty * 4 + 3) * KP_STRIDE + c];
            float4 bv = *(float4*)&Vs[c * 64 + tx * 4];
            acc[0][0] += a0 * bv.x; acc[0][1] += a0 * bv.y; acc[0][2] += a0 * bv.z; acc[0][3] += a0 * bv.w;
            acc[1][0] += a1 * bv.x; acc[1][1] += a1 * bv.y; acc[1][2] += a1 * bv.z; acc[1][3] += a1 * bv.w;
            acc[2][0] += a2 * bv.x; acc[2][1] += a2 * bv.y; acc[2][2] += a2 * bv.z; acc[2][3] += a2 * bv.w;
            acc[3][0] += a3 * bv.x; acc[3][1] += a3 * bv.y; acc[3][2] += a3 * bv.z; acc[3][3] += a3 * bv.w;
        }
        __syncthreads();  // before next tile overwrites KP/Vs
    }

    // Epilogue: normalize by l and store
    float* op = out + ((size_t)b * T_ + qt * 64) * H_;
    #pragma unroll
    for (int i = 0; i < 4; i++) {
        float inv = 1.0f / l_i[i];
        float4 v = make_float4(acc[i][0] * inv, acc[i][1] * inv,
                               acc[i][2] * inv, acc[i][3] * inv);
        *(float4*)&op[(ty * 4 + i) * 64 + tx * 4] = v;
    }
}

// ---------------------------------------------------------------------------
extern "C" void kernel_launch(void* const* d_in, const int* in_sizes, int n_in,
                              void* d_out, int out_size)
{
    const float* x  = (const float*)d_in[0];
    const float* Wq = (const float*)d_in[1];
    const float* Wk = (const float*)d_in[2];
    const float* Wv = (const float*)d_in[3];
    float* out = (float*)d_out;

    qkv_kernel<<<dim3(M_ / 64, 3), 256>>>(x, Wq, Wk, Wv);

    cudaFuncSetAttribute(attn_kernel,
                         cudaFuncAttributeMaxDynamicSharedMemorySize,
                         ATTN_SMEM_BYTES);
    attn_kernel<<<dim3(T_ / 64, B_), 256, ATTN_SMEM_BYTES>>>(out);
}

// round 2
// speedup vs baseline: 1.9062x; 1.9062x over previous
#include <cuda_runtime.h>
#include <math.h>

#define B_ 512
#define T_ 256
#define E_ 384
#define H_ 64
#define M_ (B_ * T_)   // 131072

// Scratch for projected q, k, v — static device globals, no runtime alloc.
__device__ float g_q[(size_t)M_ * H_];
__device__ float g_k[(size_t)M_ * H_];
__device__ float g_v[(size_t)M_ * H_];

__device__ __forceinline__ unsigned f2tf32(float f) {
    unsigned u;
    asm("cvt.rna.tf32.f32 %0, %1;" : "=r"(u) : "f"(f));
    return u;
}

// ---------------------------------------------------------------------------
// Kernel 1: fused QKV projection with tf32 tensor cores.
// C[64 x 192] = X[64 x 384] * [Wq|Wk|Wv][384 x 192] per block.
// 8 warps, warp tile 32x48 (2 x m16, 6 x n8), mma.sync.m16n8k8.tf32.
// ---------------------------------------------------------------------------
#define WS_STRIDE 200   // 200 mod 32 = 8 -> conflict-free B-fragment reads
#define XS_STRIDE 36    // 36 mod 32 = 4  -> conflict-free A-fragment reads

__global__ __launch_bounds__(256) void qkv_tc_kernel(
    const float* __restrict__ x,
    const float* __restrict__ Wq,
    const float* __restrict__ Wk,
    const float* __restrict__ Wv)
{
    __shared__ unsigned Xs[64][XS_STRIDE];
    __shared__ unsigned Ws[32][WS_STRIDE];

    const int tid  = threadIdx.x;
    const int warp = tid >> 5;
    const int lane = tid & 31;
    const int row0 = blockIdx.x * 64;

    const int mbase = (warp >> 2) * 32;   // 0 or 32
    const int nbase = (warp & 3) * 48;    // 0,48,96,144

    float c[2][6][4] = {};

    for (int k0 = 0; k0 < E_; k0 += 32) {
        // Load X tile 64x32 (512 float4)
        #pragma unroll
        for (int i = 0; i < 2; i++) {
            int f = tid + i * 256;
            int r = f >> 3, c4 = f & 7;
            float4 v = *(const float4*)&x[(size_t)(row0 + r) * E_ + k0 + c4 * 4];
            Xs[r][c4 * 4 + 0] = f2tf32(v.x);
            Xs[r][c4 * 4 + 1] = f2tf32(v.y);
            Xs[r][c4 * 4 + 2] = f2tf32(v.z);
            Xs[r][c4 * 4 + 3] = f2tf32(v.w);
        }
        // Load W tile 32x192: cols [0,64)=Wq, [64,128)=Wk, [128,192)=Wv
        #pragma unroll
        for (int i = 0; i < 6; i++) {
            int f = tid + i * 256;            // 0..1535
            int r = f / 48, cg = f % 48;
            int m = cg >> 4, c4 = cg & 15;
            const float* Wm = (m == 0) ? Wq : ((m == 1) ? Wk : Wv);
            float4 v = *(const float4*)&Wm[(size_t)(k0 + r) * H_ + c4 * 4];
            int col = m * 64 + c4 * 4;
            Ws[r][col + 0] = f2tf32(v.x);
            Ws[r][col + 1] = f2tf32(v.y);
            Ws[r][col + 2] = f2tf32(v.z);
            Ws[r][col + 3] = f2tf32(v.w);
        }
        __syncthreads();

        #pragma unroll
        for (int kk = 0; kk < 32; kk += 8) {
            unsigned a[2][4];
            #pragma unroll
            for (int mt = 0; mt < 2; mt++) {
                int r  = mbase + mt * 16 + (lane >> 2);
                int cc = kk + (lane & 3);
                a[mt][0] = Xs[r][cc];
                a[mt][1] = Xs[r + 8][cc];
                a[mt][2] = Xs[r][cc + 4];
                a[mt][3] = Xs[r + 8][cc + 4];
            }
            #pragma unroll
            for (int nt = 0; nt < 6; nt++) {
                int col = nbase + nt * 8 + (lane >> 2);
                int rr  = kk + (lane & 3);
                unsigned b0 = Ws[rr][col];
                unsigned b1 = Ws[rr + 4][col];
                #pragma unroll
                for (int mt = 0; mt < 2; mt++) {
                    asm volatile(
                        "mma.sync.aligned.m16n8k8.row.col.f32.tf32.tf32.f32 "
                        "{%0,%1,%2,%3}, {%4,%5,%6,%7}, {%8,%9}, {%0,%1,%2,%3};"
                        : "+f"(c[mt][nt][0]), "+f"(c[mt][nt][1]),
                          "+f"(c[mt][nt][2]), "+f"(c[mt][nt][3])
                        : "r"(a[mt][0]), "r"(a[mt][1]), "r"(a[mt][2]), "r"(a[mt][3]),
                          "r"(b0), "r"(b1));
                }
            }
        }
        __syncthreads();
    }

    // Epilogue: scatter c fragments to g_q / g_k / g_v
    #pragma unroll
    for (int mt = 0; mt < 2; mt++) {
        #pragma unroll
        for (int nt = 0; nt < 6; nt++) {
            int col = nbase + nt * 8 + (lane & 3) * 2;
            int m = col >> 6;
            int h = col & 63;
            float* o = (m == 0) ? g_q : ((m == 1) ? g_k : g_v);
            int r = row0 + mbase + mt * 16 + (lane >> 2);
            *(float2*)&o[(size_t)r * H_ + h] =
                make_float2(c[mt][nt][0], c[mt][nt][1]);
            *(float2*)&o[(size_t)(r + 8) * H_ + h] =
                make_float2(c[mt][nt][2], c[mt][nt][3]);
        }
    }
}

// ---------------------------------------------------------------------------
// Kernel 2: flash attention with online softmax (unchanged from R1).
// ---------------------------------------------------------------------------
#define KP_STRIDE 68
#define ATTN_SMEM_FLOATS (64 * 64 + 64 * KP_STRIDE + 64 * 64)
#define ATTN_SMEM_BYTES  (ATTN_SMEM_FLOATS * 4)

__global__ __launch_bounds__(256) void attn_kernel(float* __restrict__ out)
{
    extern __shared__ float sm[];
    float* Qs = sm;
    float* KP = sm + 4096;
    float* Vs = sm + 4096 + 64 * KP_STRIDE;

    const int qt = blockIdx.x;
    const int b  = blockIdx.y;
    const int tid = threadIdx.x;
    const int ty = tid >> 4;
    const int tx = tid & 15;

    const float* qp = g_q + ((size_t)b * T_ + qt * 64) * H_;
    #pragma unroll
    for (int f = tid; f < 1024; f += 256) {
        int r = f >> 4, c4 = f & 15;
        *(float4*)&Qs[r * 64 + c4 * 4] = *(const float4*)&qp[r * 64 + c4 * 4];
    }

    float acc[4][4] = {};
    float m_i[4], l_i[4];
    #pragma unroll
    for (int i = 0; i < 4; i++) { m_i[i] = -1e30f; l_i[i] = 0.0f; }

    __syncthreads();

    for (int kt = 0; kt <= qt; kt++) {
        const float* kp = g_k + ((size_t)b * T_ + kt * 64) * H_;
        const float* vp = g_v + ((size_t)b * T_ + kt * 64) * H_;

        #pragma unroll
        for (int f = tid; f < 1024; f += 256) {
            int c = f >> 4, h4 = f & 15;
            float4 kv = *(const float4*)&kp[c * 64 + h4 * 4];
            KP[(h4 * 4 + 0) * KP_STRIDE + c] = kv.x;
            KP[(h4 * 4 + 1) * KP_STRIDE + c] = kv.y;
            KP[(h4 * 4 + 2) * KP_STRIDE + c] = kv.z;
            KP[(h4 * 4 + 3) * KP_STRIDE + c] = kv.w;
            *(float4*)&Vs[c * 64 + h4 * 4] = *(const float4*)&vp[c * 64 + h4 * 4];
        }
        __syncthreads();

        float s[4][4] = {};
        #pragma unroll
        for (int h = 0; h < 64; h++) {
            float a0 = Qs[(ty * 4 + 0) * 64 + h];
            float a1 = Qs[(ty * 4 + 1) * 64 + h];
            float a2 = Qs[(ty * 4 + 2) * 64 + h];
            float a3 = Qs[(ty * 4 + 3) * 64 + h];
            float4 bv = *(float4*)&KP[h * KP_STRIDE + tx * 4];
            s[0][0] += a0 * bv.x; s[0][1] += a0 * bv.y; s[0][2] += a0 * bv.z; s[0][3] += a0 * bv.w;
            s[1][0] += a1 * bv.x; s[1][1] += a1 * bv.y; s[1][2] += a1 * bv.z; s[1][3] += a1 * bv.w;
            s[2][0] += a2 * bv.x; s[2][1] += a2 * bv.y; s[2][2] += a2 * bv.z; s[2][3] += a2 * bv.w;
            s[3][0] += a3 * bv.x; s[3][1] += a3 * bv.y; s[3][2] += a3 * bv.z; s[3][3] += a3 * bv.w;
        }

        const float scale = 0.125f;
        if (kt == qt) {
            #pragma unroll
            for (int i = 0; i < 4; i++)
                #pragma unroll
                for (int j = 0; j < 4; j++)
                    s[i][j] = (tx * 4 + j <= ty * 4 + i) ? s[i][j] * scale : -1e30f;
        } else {
            #pragma unroll
            for (int i = 0; i < 4; i++)
                #pragma unroll
                for (int j = 0; j < 4; j++)
                    s[i][j] *= scale;
        }

        float p[4][4];
        float corr[4];
        #pragma unroll
        for (int i = 0; i < 4; i++) {
            float mx = fmaxf(fmaxf(s[i][0], s[i][1]), fmaxf(s[i][2], s[i][3]));
            mx = fmaxf(mx, __shfl_xor_sync(0xffffffffu, mx, 8));
            mx = fmaxf(mx, __shfl_xor_sync(0xffffffffu, mx, 4));
            mx = fmaxf(mx, __shfl_xor_sync(0xffffffffu, mx, 2));
            mx = fmaxf(mx, __shfl_xor_sync(0xffffffffu, mx, 1));
            float mnew = fmaxf(m_i[i], mx);
            corr[i] = __expf(m_i[i] - mnew);
            p[i][0] = __expf(s[i][0] - mnew);
            p[i][1] = __expf(s[i][1] - mnew);
            p[i][2] = __expf(s[i][2] - mnew);
            p[i][3] = __expf(s[i][3] - mnew);
            float ts = p[i][0] + p[i][1] + p[i][2] + p[i][3];
            ts += __shfl_xor_sync(0xffffffffu, ts, 8);
            ts += __shfl_xor_sync(0xffffffffu, ts, 4);
            ts += __shfl_xor_sync(0xffffffffu, ts, 2);
            ts += __shfl_xor_sync(0xffffffffu, ts, 1);
            l_i[i] = l_i[i] * corr[i] + ts;
            m_i[i] = mnew;
            acc[i][0] *= corr[i]; acc[i][1] *= corr[i];
            acc[i][2] *= corr[i]; acc[i][3] *= corr[i];
        }

        __syncthreads();
        #pragma unroll
        for (int i = 0; i < 4; i++)
            *(float4*)&KP[(ty * 4 + i) * KP_STRIDE + tx * 4] =
                make_float4(p[i][0], p[i][1], p[i][2], p[i][3]);
        __syncthreads();

        #pragma unroll
        for (int c = 0; c < 64; c++) {
            float a0 = KP[(ty * 4 + 0) * KP_STRIDE + c];
            float a1 = KP[(ty * 4 + 1) * KP_STRIDE + c];
            float a2 = KP[(ty * 4 + 2) * KP_STRIDE + c];
            float a3 = KP[(ty * 4 + 3) * KP_STRIDE + c];
            float4 bv = *(float4*)&Vs[c * 64 + tx * 4];
            acc[0][0] += a0 * bv.x; acc[0][1] += a0 * bv.y; acc[0][2] += a0 * bv.z; acc[0][3] += a0 * bv.w;
            acc[1][0] += a1 * bv.x; acc[1][1] += a1 * bv.y; acc[1][2] += a1 * bv.z; acc[1][3] += a1 * bv.w;
            acc[2][0] += a2 * bv.x; acc[2][1] += a2 * bv.y; acc[2][2] += a2 * bv.z; acc[2][3] += a2 * bv.w;
            acc[3][0] += a3 * bv.x; acc[3][1] += a3 * bv.y; acc[3][2] += a3 * bv.z; acc[3][3] += a3 * bv.w;
        }
        __syncthreads();
    }

    float* op = out + ((size_t)b * T_ + qt * 64) * H_;
    #pragma unroll
    for (int i = 0; i < 4; i++) {
        float inv = 1.0f / l_i[i];
        float4 v = make_float4(acc[i][0] * inv, acc[i][1] * inv,
                               acc[i][2] * inv, acc[i][3] * inv);
        *(float4*)&op[(ty * 4 + i) * 64 + tx * 4] = v;
    }
}

// ---------------------------------------------------------------------------
extern "C" void kernel_launch(void* const* d_in, const int* in_sizes, int n_in,
                              void* d_out, int out_size)
{
    const float* x  = (const float*)d_in[0];
    const float* Wq = (const float*)d_in[1];
    const float* Wk = (const float*)d_in[2];
    const float* Wv = (const float*)d_in[3];
    float* out = (float*)d_out;

    qkv_tc_kernel<<<M_ / 64, 256>>>(x, Wq, Wk, Wv);

    cudaFuncSetAttribute(attn_kernel,
                         cudaFuncAttributeMaxDynamicSharedMemorySize,
                         ATTN_SMEM_BYTES);
    attn_kernel<<<dim3(T_ / 64, B_), 256, ATTN_SMEM_BYTES>>>(out);
}

// round 3
// speedup vs baseline: 2.6122x; 1.3704x over previous
#include <cuda_runtime.h>
#include <math.h>

#define B_ 512
#define T_ 256
#define E_ 384
#define H_ 64
#define M_ (B_ * T_)   // 131072

// Scratch for projected q, k, v — static device globals, no runtime alloc.
__device__ float g_q[(size_t)M_ * H_];
__device__ float g_k[(size_t)M_ * H_];
__device__ float g_v[(size_t)M_ * H_];

__device__ __forceinline__ unsigned f2tf32(float f) {
    unsigned u;
    asm("cvt.rna.tf32.f32 %0, %1;" : "=r"(u) : "f"(f));
    return u;
}

#define MMA_TF32(C, A, B0, B1)                                              \
    asm volatile(                                                           \
        "mma.sync.aligned.m16n8k8.row.col.f32.tf32.tf32.f32 "               \
        "{%0,%1,%2,%3}, {%4,%5,%6,%7}, {%8,%9}, {%0,%1,%2,%3};"             \
        : "+f"((C)[0]), "+f"((C)[1]), "+f"((C)[2]), "+f"((C)[3])            \
        : "r"((A)[0]), "r"((A)[1]), "r"((A)[2]), "r"((A)[3]),               \
          "r"(B0), "r"(B1))

// ---------------------------------------------------------------------------
// Kernel 1: fused QKV projection with tf32 tensor cores (unchanged from R2).
// ---------------------------------------------------------------------------
#define WS_STRIDE 200
#define XS_STRIDE 36

__global__ __launch_bounds__(256) void qkv_tc_kernel(
    const float* __restrict__ x,
    const float* __restrict__ Wq,
    const float* __restrict__ Wk,
    const float* __restrict__ Wv)
{
    __shared__ unsigned Xs[64][XS_STRIDE];
    __shared__ unsigned Ws[32][WS_STRIDE];

    const int tid  = threadIdx.x;
    const int warp = tid >> 5;
    const int lane = tid & 31;
    const int row0 = blockIdx.x * 64;

    const int mbase = (warp >> 2) * 32;
    const int nbase = (warp & 3) * 48;

    float c[2][6][4] = {};

    for (int k0 = 0; k0 < E_; k0 += 32) {
        #pragma unroll
        for (int i = 0; i < 2; i++) {
            int f = tid + i * 256;
            int r = f >> 3, c4 = f & 7;
            float4 v = *(const float4*)&x[(size_t)(row0 + r) * E_ + k0 + c4 * 4];
            Xs[r][c4 * 4 + 0] = f2tf32(v.x);
            Xs[r][c4 * 4 + 1] = f2tf32(v.y);
            Xs[r][c4 * 4 + 2] = f2tf32(v.z);
            Xs[r][c4 * 4 + 3] = f2tf32(v.w);
        }
        #pragma unroll
        for (int i = 0; i < 6; i++) {
            int f = tid + i * 256;
            int r = f / 48, cg = f % 48;
            int m = cg >> 4, c4 = cg & 15;
            const float* Wm = (m == 0) ? Wq : ((m == 1) ? Wk : Wv);
            float4 v = *(const float4*)&Wm[(size_t)(k0 + r) * H_ + c4 * 4];
            int col = m * 64 + c4 * 4;
            Ws[r][col + 0] = f2tf32(v.x);
            Ws[r][col + 1] = f2tf32(v.y);
            Ws[r][col + 2] = f2tf32(v.z);
            Ws[r][col + 3] = f2tf32(v.w);
        }
        __syncthreads();

        #pragma unroll
        for (int kk = 0; kk < 32; kk += 8) {
            unsigned a[2][4];
            #pragma unroll
            for (int mt = 0; mt < 2; mt++) {
                int r  = mbase + mt * 16 + (lane >> 2);
                int cc = kk + (lane & 3);
                a[mt][0] = Xs[r][cc];
                a[mt][1] = Xs[r + 8][cc];
                a[mt][2] = Xs[r][cc + 4];
                a[mt][3] = Xs[r + 8][cc + 4];
            }
            #pragma unroll
            for (int nt = 0; nt < 6; nt++) {
                int col = nbase + nt * 8 + (lane >> 2);
                int rr  = kk + (lane & 3);
                unsigned b0 = Ws[rr][col];
                unsigned b1 = Ws[rr + 4][col];
                #pragma unroll
                for (int mt = 0; mt < 2; mt++)
                    MMA_TF32(c[mt][nt], a[mt], b0, b1);
            }
        }
        __syncthreads();
    }

    #pragma unroll
    for (int mt = 0; mt < 2; mt++) {
        #pragma unroll
        for (int nt = 0; nt < 6; nt++) {
            int col = nbase + nt * 8 + (lane & 3) * 2;
            int m = col >> 6;
            int h = col & 63;
            float* o = (m == 0) ? g_q : ((m == 1) ? g_k : g_v);
            int r = row0 + mbase + mt * 16 + (lane >> 2);
            *(float2*)&o[(size_t)r * H_ + h] =
                make_float2(c[mt][nt][0], c[mt][nt][1]);
            *(float2*)&o[(size_t)(r + 8) * H_ + h] =
                make_float2(c[mt][nt][2], c[mt][nt][3]);
        }
    }
}

// ---------------------------------------------------------------------------
// Kernel 2: flash attention, tf32 tensor cores.
// grid = (T/128, B); 8 warps; each warp owns 16 q-rows (full 64-wide k tiles).
// smem: Ks[64][68] | Vs[64][68] (transposed) | Ps[128][68] (= Q staging).
// ---------------------------------------------------------------------------
#define KSTR 68
#define ATTN_SMEM_BYTES (256 * KSTR * 4)   // 69632

__global__ __launch_bounds__(256, 2) void attn_tc_kernel(float* __restrict__ out)
{
    extern __shared__ unsigned sm[];
    unsigned* Ks = sm;                  // 64 x KSTR
    unsigned* Vs = sm + 64 * KSTR;      // 64 x KSTR  (Vs[h][c])
    unsigned* Ps = sm + 128 * KSTR;     // 128 x KSTR (also Q staging)
    unsigned* Qs = Ps;

    const int tid  = threadIdx.x;
    const int warp = tid >> 5;
    const int lane = tid & 31;
    const int rq   = lane >> 2;         // 0..7
    const int qq   = lane & 3;          // 0..3
    const int q0   = blockIdx.x * 128;
    const int b    = blockIdx.y;

    // --- Stage Q (scaled by 1/sqrt(d), tf32) ---
    const float* qp = g_q + ((size_t)b * T_ + q0) * H_;
    #pragma unroll
    for (int i = 0; i < 8; i++) {
        int f = tid + i * 256;
        int r = f >> 4, h4 = f & 15;
        float4 v = *(const float4*)&qp[r * 64 + h4 * 4];
        Qs[r * KSTR + h4 * 4 + 0] = f2tf32(v.x * 0.125f);
        Qs[r * KSTR + h4 * 4 + 1] = f2tf32(v.y * 0.125f);
        Qs[r * KSTR + h4 * 4 + 2] = f2tf32(v.z * 0.125f);
        Qs[r * KSTR + h4 * 4 + 3] = f2tf32(v.w * 0.125f);
    }
    __syncthreads();

    // --- Q fragments into registers ---
    const int lr = warp * 16 + rq;      // local row (0..127)
    unsigned qf[8][4];
    #pragma unroll
    for (int k8 = 0; k8 < 8; k8++) {
        qf[k8][0] = Qs[lr * KSTR + k8 * 8 + qq];
        qf[k8][1] = Qs[(lr + 8) * KSTR + k8 * 8 + qq];
        qf[k8][2] = Qs[lr * KSTR + k8 * 8 + qq + 4];
        qf[k8][3] = Qs[(lr + 8) * KSTR + k8 * 8 + qq + 4];
    }

    float o[8][4] = {};
    float m0 = -1e30f, m1 = -1e30f, l0 = 0.0f, l1 = 0.0f;

    const int row_min = q0 + warp * 16;
    const int row_max = row_min + 15;
    const int r0g = row_min + rq;       // global row for "r"; "+8" row = r0g+8
    const int ktmax = (q0 + 127) >> 6;

    const float* kp = g_k + (size_t)b * T_ * H_;
    const float* vp = g_v + (size_t)b * T_ * H_;

    for (int kt = 0; kt <= ktmax; kt++) {
        // Load K tile [c][h], tf32  (coalesced float4 reads, uint stores)
        #pragma unroll
        for (int i = 0; i < 4; i++) {
            int f = tid + i * 256;
            int c = f >> 4, h4 = f & 15;
            float4 v = *(const float4*)&kp[(size_t)(kt * 64 + c) * 64 + h4 * 4];
            Ks[c * KSTR + h4 * 4 + 0] = f2tf32(v.x);
            Ks[c * KSTR + h4 * 4 + 1] = f2tf32(v.y);
            Ks[c * KSTR + h4 * 4 + 2] = f2tf32(v.z);
            Ks[c * KSTR + h4 * 4 + 3] = f2tf32(v.w);
        }
        // Load V tile transposed Vs[h][c]  (c-major thread map -> conflict-free stores)
        #pragma unroll
        for (int i = 0; i < 4; i++) {
            int f = tid + i * 256;
            int h4 = f >> 6, c = f & 63;
            float4 v = *(const float4*)&vp[(size_t)(kt * 64 + c) * 64 + h4 * 4];
            Vs[(h4 * 4 + 0) * KSTR + c] = f2tf32(v.x);
            Vs[(h4 * 4 + 1) * KSTR + c] = f2tf32(v.y);
            Vs[(h4 * 4 + 2) * KSTR + c] = f2tf32(v.z);
            Vs[(h4 * 4 + 3) * KSTR + c] = f2tf32(v.w);
        }
        __syncthreads();

        if (kt * 64 <= row_max) {   // warp-uniform: skip fully-masked tiles
            // S = Q K^T  (s scaled already via Q)
            float s[8][4] = {};
            #pragma unroll
            for (int nt = 0; nt < 8; nt++) {
                #pragma unroll
                for (int k8 = 0; k8 < 8; k8++) {
                    unsigned b0 = Ks[(nt * 8 + rq) * KSTR + k8 * 8 + qq];
                    unsigned b1 = Ks[(nt * 8 + rq) * KSTR + k8 * 8 + qq + 4];
                    MMA_TF32(s[nt], qf[k8], b0, b1);
                }
            }

            // Causal mask (only when tile touches the diagonal for this warp)
            if (kt * 64 + 63 > row_min) {
                int colb = kt * 64 + 2 * qq;
                #pragma unroll
                for (int nt = 0; nt < 8; nt++) {
                    int c0 = colb + nt * 8, c1 = c0 + 1;
                    if (c0 > r0g)     s[nt][0] = -1e30f;
                    if (c1 > r0g)     s[nt][1] = -1e30f;
                    if (c0 > r0g + 8) s[nt][2] = -1e30f;
                    if (c1 > r0g + 8) s[nt][3] = -1e30f;
                }
            }

            // Online softmax (rows r, r+8; quad reduction)
            float mx0 = -1e30f, mx1 = -1e30f;
            #pragma unroll
            for (int nt = 0; nt < 8; nt++) {
                mx0 = fmaxf(mx0, fmaxf(s[nt][0], s[nt][1]));
                mx1 = fmaxf(mx1, fmaxf(s[nt][2], s[nt][3]));
            }
            mx0 = fmaxf(mx0, __shfl_xor_sync(0xffffffffu, mx0, 1));
            mx0 = fmaxf(mx0, __shfl_xor_sync(0xffffffffu, mx0, 2));
            mx1 = fmaxf(mx1, __shfl_xor_sync(0xffffffffu, mx1, 1));
            mx1 = fmaxf(mx1, __shfl_xor_sync(0xffffffffu, mx1, 2));

            float mn0 = fmaxf(m0, mx0), mn1 = fmaxf(m1, mx1);
            float cr0 = __expf(m0 - mn0), cr1 = __expf(m1 - mn1);
            float sum0 = 0.0f, sum1 = 0.0f;
            #pragma unroll
            for (int nt = 0; nt < 8; nt++) {
                s[nt][0] = __expf(s[nt][0] - mn0);
                s[nt][1] = __expf(s[nt][1] - mn0);
                s[nt][2] = __expf(s[nt][2] - mn1);
                s[nt][3] = __expf(s[nt][3] - mn1);
                sum0 += s[nt][0] + s[nt][1];
                sum1 += s[nt][2] + s[nt][3];
            }
            sum0 += __shfl_xor_sync(0xffffffffu, sum0, 1);
            sum0 += __shfl_xor_sync(0xffffffffu, sum0, 2);
            sum1 += __shfl_xor_sync(0xffffffffu, sum1, 1);
            sum1 += __shfl_xor_sync(0xffffffffu, sum1, 2);

            l0 = l0 * cr0 + sum0;  l1 = l1 * cr1 + sum1;
            m0 = mn0;              m1 = mn1;
            #pragma unroll
            for (int nt = 0; nt < 8; nt++) {
                o[nt][0] *= cr0; o[nt][1] *= cr0;
                o[nt][2] *= cr1; o[nt][3] *= cr1;
            }

            // P -> smem (tf32), re-fragment as A for PV
            #pragma unroll
            for (int nt = 0; nt < 8; nt++) {
                Ps[lr * KSTR + nt * 8 + 2 * qq + 0]       = f2tf32(s[nt][0]);
                Ps[lr * KSTR + nt * 8 + 2 * qq + 1]       = f2tf32(s[nt][1]);
                Ps[(lr + 8) * KSTR + nt * 8 + 2 * qq + 0] = f2tf32(s[nt][2]);
                Ps[(lr + 8) * KSTR + nt * 8 + 2 * qq + 1] = f2tf32(s[nt][3]);
            }
            __syncwarp();

            unsigned af[8][4];
            #pragma unroll
            for (int k8 = 0; k8 < 8; k8++) {
                af[k8][0] = Ps[lr * KSTR + k8 * 8 + qq];
                af[k8][1] = Ps[(lr + 8) * KSTR + k8 * 8 + qq];
                af[k8][2] = Ps[lr * KSTR + k8 * 8 + qq + 4];
                af[k8][3] = Ps[(lr + 8) * KSTR + k8 * 8 + qq + 4];
            }

            // O += P V
            #pragma unroll
            for (int nt = 0; nt < 8; nt++) {
                #pragma unroll
                for (int k8 = 0; k8 < 8; k8++) {
                    unsigned b0 = Vs[(nt * 8 + rq) * KSTR + k8 * 8 + qq];
                    unsigned b1 = Vs[(nt * 8 + rq) * KSTR + k8 * 8 + qq + 4];
                    MMA_TF32(o[nt], af[k8], b0, b1);
                }
            }
        }
        __syncthreads();
    }

    // Epilogue
    float inv0 = 1.0f / l0, inv1 = 1.0f / l1;
    float* op0 = out + ((size_t)b * T_ + q0 + lr) * 64;
    float* op1 = out + ((size_t)b * T_ + q0 + lr + 8) * 64;
    #pragma unroll
    for (int nt = 0; nt < 8; nt++) {
        int col = nt * 8 + 2 * qq;
        *(float2*)&op0[col] = make_float2(o[nt][0] * inv0, o[nt][1] * inv0);
        *(float2*)&op1[col] = make_float2(o[nt][2] * inv1, o[nt][3] * inv1);
    }
}

// ---------------------------------------------------------------------------
extern "C" void kernel_launch(void* const* d_in, const int* in_sizes, int n_in,
                              void* d_out, int out_size)
{
    const float* x  = (const float*)d_in[0];
    const float* Wq = (const float*)d_in[1];
    const float* Wk = (const float*)d_in[2];
    const float* Wv = (const float*)d_in[3];
    float* out = (float*)d_out;

    qkv_tc_kernel<<<M_ / 64, 256>>>(x, Wq, Wk, Wv);

    cudaFuncSetAttribute(attn_tc_kernel,
                         cudaFuncAttributeMaxDynamicSharedMemorySize,
                         ATTN_SMEM_BYTES);
    attn_tc_kernel<<<dim3(T_ / 128, B_), 256, ATTN_SMEM_BYTES>>>(out);
}

// round 6
// speedup vs baseline: 2.9725x; 1.1379x over previous
#include <cuda_runtime.h>
#include <math.h>
#include <stdint.h>

#define B_ 512
#define T_ 256
#define E_ 384
#define H_ 64
#define M_ (B_ * T_)   // 131072

__device__ float g_q[(size_t)M_ * H_];
__device__ float g_k[(size_t)M_ * H_];
__device__ float g_v[(size_t)M_ * H_];
__device__ unsigned g_wt[384 * 192];   // [k][n], n = m*64+h, tf32-rounded

__device__ __forceinline__ unsigned f2tf32(float f) {
    unsigned u;
    asm("cvt.rna.tf32.f32 %0, %1;" : "=r"(u) : "f"(f));
    return u;
}
__device__ __forceinline__ unsigned u2tf32(unsigned x) {
    unsigned u;
    asm("cvt.rna.tf32.f32 %0, %1;" : "=r"(u) : "f"(__uint_as_float(x)));
    return u;
}
__device__ __forceinline__ uint32_t s2u(const void* p) {
    uint32_t a;
    asm("{ .reg .u64 t; cvta.to.shared.u64 t, %1; cvt.u32.u64 %0, t; }"
        : "=r"(a) : "l"(p));
    return a;
}
__device__ __forceinline__ void cpa16(uint32_t dst, const void* src) {
    asm volatile("cp.async.cg.shared.global [%0], [%1], 16;"
                 :: "r"(dst), "l"(src) : "memory");
}

#define MMA_TF32(C, A, B0, B1)                                              \
    asm volatile(                                                           \
        "mma.sync.aligned.m16n8k8.row.col.f32.tf32.tf32.f32 "               \
        "{%0,%1,%2,%3}, {%4,%5,%6,%7}, {%8,%9}, {%0,%1,%2,%3};"             \
        : "+f"((C)[0]), "+f"((C)[1]), "+f"((C)[2]), "+f"((C)[3])            \
        : "r"((A)[0]), "r"((A)[1]), "r"((A)[2]), "r"((A)[3]),               \
          "r"(B0), "r"(B1))

// ---------------------------------------------------------------------------
// Kernel 0: W -> tf32, interleaved layout g_wt[k][n], n = m*64 + h
// ---------------------------------------------------------------------------
__global__ __launch_bounds__(256) void wt_kernel(
    const float* __restrict__ Wq, const float* __restrict__ Wk,
    const float* __restrict__ Wv)
{
    int idx = blockIdx.x * 256 + threadIdx.x;   // 0..73727
    int k = idx / 192, n = idx % 192;
    const float* Wm = (n < 64) ? Wq : ((n < 128) ? Wk : Wv);
    g_wt[idx] = f2tf32(Wm[(size_t)k * 64 + (n & 63)]);
}

// ---------------------------------------------------------------------------
// Kernel 1: fused QKV projection, legacy tf32 mma + cp.async double buffer.
// CTA: 128 rows x 192 cols, K-chunks of 32. 512 threads, warp tile 32x48.
// smem (dynamic): Xs[2][128][36] | Ws[2][32][200]
// x staged raw fp32, RNA-rounded to tf32 at fragment-read time.
// ---------------------------------------------------------------------------
#define XT_STRIDE 36
#define WT_STRIDE 200
#define XS_FLOATS (128 * XT_STRIDE)
#define WS_FLOATS (32 * WT_STRIDE)
#define WS_BASE   (2 * XS_FLOATS)
#define QKV_SMEM_BYTES ((2 * XS_FLOATS + 2 * WS_FLOATS) * 4)   // 88064

__global__ __launch_bounds__(512, 1) void qkv_tc2_kernel(const float* __restrict__ x)
{
    extern __shared__ __align__(16) unsigned sm[];
    const uint32_t sb = s2u(sm);
    const int tid  = threadIdx.x;
    const int warp = tid >> 5;
    const int lane = tid & 31;
    const int row0 = blockIdx.x * 128;

    const int mbase = (warp >> 2) * 32;   // 0,32,64,96
    const int nbase = (warp & 3) * 48;    // 0,48,96,144

    const float* xp = x + (size_t)row0 * E_;

    auto prefetch = [&](int s, int kb) {
        const uint32_t xbase = sb + (s * XS_FLOATS) * 4;
        #pragma unroll
        for (int i = 0; i < 2; i++) {
            int f = tid + i * 512;
            int r = f >> 3, c4 = f & 7;
            cpa16(xbase + (r * XT_STRIDE + c4 * 4) * 4,
                  xp + (size_t)r * E_ + kb * 32 + c4 * 4);
        }
        const uint32_t wbase = sb + (WS_BASE + s * WS_FLOATS) * 4;
        #pragma unroll
        for (int i = 0; i < 3; i++) {
            int f = tid + i * 512;
            int r = f / 48, c4 = f % 48;
            cpa16(wbase + (r * WT_STRIDE + c4 * 4) * 4,
                  g_wt + (size_t)(kb * 32 + r) * 192 + c4 * 4);
        }
        asm volatile("cp.async.commit_group;" ::: "memory");
    };

    float c[2][6][4] = {};

    prefetch(0, 0);

    for (int kb = 0; kb < 12; kb++) {
        const int s = kb & 1;
        if (kb + 1 < 12) {
            prefetch(s ^ 1, kb + 1);
            asm volatile("cp.async.wait_group 1;" ::: "memory");
        } else {
            asm volatile("cp.async.wait_group 0;" ::: "memory");
        }
        __syncthreads();

        const unsigned* Xs = sm + s * XS_FLOATS;
        const unsigned* Ws = sm + WS_BASE + s * WS_FLOATS;

        #pragma unroll
        for (int kk = 0; kk < 32; kk += 8) {
            unsigned a[2][4];
            #pragma unroll
            for (int mt = 0; mt < 2; mt++) {
                int r  = mbase + mt * 16 + (lane >> 2);
                int cc = kk + (lane & 3);
                a[mt][0] = u2tf32(Xs[r * XT_STRIDE + cc]);
                a[mt][1] = u2tf32(Xs[(r + 8) * XT_STRIDE + cc]);
                a[mt][2] = u2tf32(Xs[r * XT_STRIDE + cc + 4]);
                a[mt][3] = u2tf32(Xs[(r + 8) * XT_STRIDE + cc + 4]);
            }
            #pragma unroll
            for (int nt = 0; nt < 6; nt++) {
                int col = nbase + nt * 8 + (lane >> 2);
                int rr  = kk + (lane & 3);
                unsigned b0 = Ws[rr * WT_STRIDE + col];
                unsigned b1 = Ws[(rr + 4) * WT_STRIDE + col];
                #pragma unroll
                for (int mt = 0; mt < 2; mt++)
                    MMA_TF32(c[mt][nt], a[mt], b0, b1);
            }
        }
        __syncthreads();
    }

    #pragma unroll
    for (int mt = 0; mt < 2; mt++) {
        #pragma unroll
        for (int nt = 0; nt < 6; nt++) {
            int col = nbase + nt * 8 + (lane & 3) * 2;
            int m = col >> 6;
            int h = col & 63;
            float* o = (m == 0) ? g_q : ((m == 1) ? g_k : g_v);
            int r = row0 + mbase + mt * 16 + (lane >> 2);
            *(float2*)&o[(size_t)r * H_ + h] =
                make_float2(c[mt][nt][0], c[mt][nt][1]);
            *(float2*)&o[(size_t)(r + 8) * H_ + h] =
                make_float2(c[mt][nt][2], c[mt][nt][3]);
        }
    }
}

// ---------------------------------------------------------------------------
// Kernel 2: flash attention, legacy tf32 mma (unchanged from R3, 77.7us).
// ---------------------------------------------------------------------------
#define KSTR 68
#define ATTN_SMEM_BYTES (256 * KSTR * 4)

__global__ __launch_bounds__(256, 2) void attn_tc_kernel(float* __restrict__ out)
{
    extern __shared__ unsigned smA[];
    unsigned* Ks = smA;
    unsigned* Vs = smA + 64 * KSTR;
    unsigned* Ps = smA + 128 * KSTR;
    unsigned* Qs = Ps;

    const int tid  = threadIdx.x;
    const int warp = tid >> 5;
    const int lane = tid & 31;
    const int rq   = lane >> 2;
    const int qq   = lane & 3;
    const int q0   = blockIdx.x * 128;
    const int b    = blockIdx.y;

    const float* qp = g_q + ((size_t)b * T_ + q0) * H_;
    #pragma unroll
    for (int i = 0; i < 8; i++) {
        int f = tid + i * 256;
        int r = f >> 4, h4 = f & 15;
        float4 v = *(const float4*)&qp[r * 64 + h4 * 4];
        Qs[r * KSTR + h4 * 4 + 0] = f2tf32(v.x * 0.125f);
        Qs[r * KSTR + h4 * 4 + 1] = f2tf32(v.y * 0.125f);
        Qs[r * KSTR + h4 * 4 + 2] = f2tf32(v.z * 0.125f);
        Qs[r * KSTR + h4 * 4 + 3] = f2tf32(v.w * 0.125f);
    }
    __syncthreads();

    const int lr = warp * 16 + rq;
    unsigned qf[8][4];
    #pragma unroll
    for (int k8 = 0; k8 < 8; k8++) {
        qf[k8][0] = Qs[lr * KSTR + k8 * 8 + qq];
        qf[k8][1] = Qs[(lr + 8) * KSTR + k8 * 8 + qq];
        qf[k8][2] = Qs[lr * KSTR + k8 * 8 + qq + 4];
        qf[k8][3] = Qs[(lr + 8) * KSTR + k8 * 8 + qq + 4];
    }

    float o[8][4] = {};
    float m0 = -1e30f, m1 = -1e30f, l0 = 0.0f, l1 = 0.0f;

    const int row_min = q0 + warp * 16;
    const int row_max = row_min + 15;
    const int r0g = row_min + rq;
    const int ktmax = (q0 + 127) >> 6;

    const float* kp = g_k + (size_t)b * T_ * H_;
    const float* vp = g_v + (size_t)b * T_ * H_;

    for (int kt = 0; kt <= ktmax; kt++) {
        #pragma unroll
        for (int i = 0; i < 4; i++) {
            int f = tid + i * 256;
            int cc = f >> 4, h4 = f & 15;
            float4 v = *(const float4*)&kp[(size_t)(kt * 64 + cc) * 64 + h4 * 4];
            Ks[cc * KSTR + h4 * 4 + 0] = f2tf32(v.x);
            Ks[cc * KSTR + h4 * 4 + 1] = f2tf32(v.y);
            Ks[cc * KSTR + h4 * 4 + 2] = f2tf32(v.z);
            Ks[cc * KSTR + h4 * 4 + 3] = f2tf32(v.w);
        }
        #pragma unroll
        for (int i = 0; i < 4; i++) {
            int f = tid + i * 256;
            int h4 = f >> 6, cc = f & 63;
            float4 v = *(const float4*)&vp[(size_t)(kt * 64 + cc) * 64 + h4 * 4];
            Vs[(h4 * 4 + 0) * KSTR + cc] = f2tf32(v.x);
            Vs[(h4 * 4 + 1) * KSTR + cc] = f2tf32(v.y);
            Vs[(h4 * 4 + 2) * KSTR + cc] = f2tf32(v.z);
            Vs[(h4 * 4 + 3) * KSTR + cc] = f2tf32(v.w);
        }
        __syncthreads();

        if (kt * 64 <= row_max) {
            float s[8][4] = {};
            #pragma unroll
            for (int nt = 0; nt < 8; nt++) {
                #pragma unroll
                for (int k8 = 0; k8 < 8; k8++) {
                    unsigned b0 = Ks[(nt * 8 + rq) * KSTR + k8 * 8 + qq];
                    unsigned b1 = Ks[(nt * 8 + rq) * KSTR + k8 * 8 + qq + 4];
                    MMA_TF32(s[nt], qf[k8], b0, b1);
                }
            }

            if (kt * 64 + 63 > row_min) {
                int colb = kt * 64 + 2 * qq;
                #pragma unroll
                for (int nt = 0; nt < 8; nt++) {
                    int c0 = colb + nt * 8, c1 = c0 + 1;
                    if (c0 > r0g)     s[nt][0] = -1e30f;
                    if (c1 > r0g)     s[nt][1] = -1e30f;
                    if (c0 > r0g + 8) s[nt][2] = -1e30f;
                    if (c1 > r0g + 8) s[nt][3] = -1e30f;
                }
            }

            float mx0 = -1e30f, mx1 = -1e30f;
            #pragma unroll
            for (int nt = 0; nt < 8; nt++) {
                mx0 = fmaxf(mx0, fmaxf(s[nt][0], s[nt][1]));
                mx1 = fmaxf(mx1, fmaxf(s[nt][2], s[nt][3]));
            }
            mx0 = fmaxf(mx0, __shfl_xor_sync(0xffffffffu, mx0, 1));
            mx0 = fmaxf(mx0, __shfl_xor_sync(0xffffffffu, mx0, 2));
            mx1 = fmaxf(mx1, __shfl_xor_sync(0xffffffffu, mx1, 1));
            mx1 = fmaxf(mx1, __shfl_xor_sync(0xffffffffu, mx1, 2));

            float mn0 = fmaxf(m0, mx0), mn1 = fmaxf(m1, mx1);
            float cr0 = __expf(m0 - mn0), cr1 = __expf(m1 - mn1);
            float sum0 = 0.0f, sum1 = 0.0f;
            #pragma unroll
            for (int nt = 0; nt < 8; nt++) {
                s[nt][0] = __expf(s[nt][0] - mn0);
                s[nt][1] = __expf(s[nt][1] - mn0);
                s[nt][2] = __expf(s[nt][2] - mn1);
                s[nt][3] = __expf(s[nt][3] - mn1);
                sum0 += s[nt][0] + s[nt][1];
                sum1 += s[nt][2] + s[nt][3];
            }
            sum0 += __shfl_xor_sync(0xffffffffu, sum0, 1);
            sum0 += __shfl_xor_sync(0xffffffffu, sum0, 2);
            sum1 += __shfl_xor_sync(0xffffffffu, sum1, 1);
            sum1 += __shfl_xor_sync(0xffffffffu, sum1, 2);

            l0 = l0 * cr0 + sum0;  l1 = l1 * cr1 + sum1;
            m0 = mn0;              m1 = mn1;
            #pragma unroll
            for (int nt = 0; nt < 8; nt++) {
                o[nt][0] *= cr0; o[nt][1] *= cr0;
                o[nt][2] *= cr1; o[nt][3] *= cr1;
            }

            #pragma unroll
            for (int nt = 0; nt < 8; nt++) {
                Ps[lr * KSTR + nt * 8 + 2 * qq + 0]       = f2tf32(s[nt][0]);
                Ps[lr * KSTR + nt * 8 + 2 * qq + 1]       = f2tf32(s[nt][1]);
                Ps[(lr + 8) * KSTR + nt * 8 + 2 * qq + 0] = f2tf32(s[nt][2]);
                Ps[(lr + 8) * KSTR + nt * 8 + 2 * qq + 1] = f2tf32(s[nt][3]);
            }
            __syncwarp();

            unsigned af[8][4];
            #pragma unroll
            for (int k8 = 0; k8 < 8; k8++) {
                af[k8][0] = Ps[lr * KSTR + k8 * 8 + qq];
                af[k8][1] = Ps[(lr + 8) * KSTR + k8 * 8 + qq];
                af[k8][2] = Ps[lr * KSTR + k8 * 8 + qq + 4];
                af[k8][3] = Ps[(lr + 8) * KSTR + k8 * 8 + qq + 4];
            }

            #pragma unroll
            for (int nt = 0; nt < 8; nt++) {
                #pragma unroll
                for (int k8 = 0; k8 < 8; k8++) {
                    unsigned b0 = Vs[(nt * 8 + rq) * KSTR + k8 * 8 + qq];
                    unsigned b1 = Vs[(nt * 8 + rq) * KSTR + k8 * 8 + qq + 4];
                    MMA_TF32(o[nt], af[k8], b0, b1);
                }
            }
        }
        __syncthreads();
    }

    float inv0 = 1.0f / l0, inv1 = 1.0f / l1;
    float* op0 = out + ((size_t)b * T_ + q0 + lr) * 64;
    float* op1 = out + ((size_t)b * T_ + q0 + lr + 8) * 64;
    #pragma unroll
    for (int nt = 0; nt < 8; nt++) {
        int col = nt * 8 + 2 * qq;
        *(float2*)&op0[col] = make_float2(o[nt][0] * inv0, o[nt][1] * inv0);
        *(float2*)&op1[col] = make_float2(o[nt][2] * inv1, o[nt][3] * inv1);
    }
}

// ---------------------------------------------------------------------------
extern "C" void kernel_launch(void* const* d_in, const int* in_sizes, int n_in,
                              void* d_out, int out_size)
{
    const float* x  = (const float*)d_in[0];
    const float* Wq = (const float*)d_in[1];
    const float* Wk = (const float*)d_in[2];
    const float* Wv = (const float*)d_in[3];
    float* out = (float*)d_out;

    wt_kernel<<<288, 256>>>(Wq, Wk, Wv);

    cudaFuncSetAttribute(qkv_tc2_kernel,
                         cudaFuncAttributeMaxDynamicSharedMemorySize,
                         QKV_SMEM_BYTES);
    qkv_tc2_kernel<<<M_ / 128, 512, QKV_SMEM_BYTES>>>(x);

    cudaFuncSetAttribute(attn_tc_kernel,
                         cudaFuncAttributeMaxDynamicSharedMemorySize,
                         ATTN_SMEM_BYTES);
    attn_tc_kernel<<<dim3(T_ / 128, B_), 256, ATTN_SMEM_BYTES>>>(out);
}